// round 2
// baseline (speedup 1.0000x reference)
#include <cuda_runtime.h>
#include <cuda_bf16.h>
#include <math.h>

// Problem constants
#define SS   512
#define BB   32
#define DD   1024
#define HH   1024
#define G4H  4096          // 4*H
#define BH   (BB*HH)       // 32768

// ---------------- scratch: X = layer_input @ U^T + bias  [S*B, 4H] ----------
__device__ float g_X[(size_t)SS * BB * G4H];   // 256 MB

// ============================================================================
// Kernel A: SGEMM (NT): X[m][n] = sum_k A[m][k] * W[n][k] + bih[n] + bhh[n]
//   A = layer_input [16384, 1024], W = U [4096, 1024]
//   128x128 tile, BK=16, 256 threads, 8x8 per thread (split 4+4).
// ============================================================================
__global__ void __launch_bounds__(256) gemm_x_kernel(
    const float* __restrict__ A,
    const float* __restrict__ W,
    const float* __restrict__ bih,
    const float* __restrict__ bhh,
    float* __restrict__ X)
{
    __shared__ float As[16][128];
    __shared__ float Bs[16][128];

    const int bm = blockIdx.y * 128;
    const int bn = blockIdx.x * 128;
    const int tid = threadIdx.x;
    const int tx = tid & 15;        // 0..15 -> columns
    const int ty = tid >> 4;        // 0..15 -> rows

    const int lr = tid >> 2;        // 0..63 row within tile (and +64)
    const int lc = (tid & 3) * 4;   // k offset 0,4,8,12

    const float* Aptr = A + (size_t)(bm + lr) * DD + lc;
    const float* Wptr = W + (size_t)(bn + lr) * DD + lc;

    float acc[8][8];
    #pragma unroll
    for (int i = 0; i < 8; i++)
        #pragma unroll
        for (int j = 0; j < 8; j++) acc[i][j] = 0.f;

    for (int k0 = 0; k0 < DD; k0 += 16) {
        float4 a0 = *(const float4*)(Aptr + k0);
        float4 a1 = *(const float4*)(Aptr + (size_t)64 * DD + k0);
        float4 w0 = *(const float4*)(Wptr + k0);
        float4 w1 = *(const float4*)(Wptr + (size_t)64 * DD + k0);

        __syncthreads();
        As[lc+0][lr]    = a0.x; As[lc+1][lr]    = a0.y; As[lc+2][lr]    = a0.z; As[lc+3][lr]    = a0.w;
        As[lc+0][lr+64] = a1.x; As[lc+1][lr+64] = a1.y; As[lc+2][lr+64] = a1.z; As[lc+3][lr+64] = a1.w;
        Bs[lc+0][lr]    = w0.x; Bs[lc+1][lr]    = w0.y; Bs[lc+2][lr]    = w0.z; Bs[lc+3][lr]    = w0.w;
        Bs[lc+0][lr+64] = w1.x; Bs[lc+1][lr+64] = w1.y; Bs[lc+2][lr+64] = w1.z; Bs[lc+3][lr+64] = w1.w;
        __syncthreads();

        #pragma unroll
        for (int kk = 0; kk < 16; kk++) {
            float ar[8], br[8];
            *(float4*)&ar[0] = *(const float4*)&As[kk][ty * 4];
            *(float4*)&ar[4] = *(const float4*)&As[kk][ty * 4 + 64];
            *(float4*)&br[0] = *(const float4*)&Bs[kk][tx * 4];
            *(float4*)&br[4] = *(const float4*)&Bs[kk][tx * 4 + 64];
            #pragma unroll
            for (int i = 0; i < 8; i++)
                #pragma unroll
                for (int j = 0; j < 8; j++)
                    acc[i][j] += ar[i] * br[j];
        }
    }

    // epilogue with fused bias
    const int gn0 = bn + tx * 4;
    float b0[4], b1[4];
    #pragma unroll
    for (int j = 0; j < 4; j++) {
        b0[j] = bih[gn0 + j]      + bhh[gn0 + j];
        b1[j] = bih[gn0 + 64 + j] + bhh[gn0 + 64 + j];
    }

    #pragma unroll
    for (int ii = 0; ii < 8; ii++) {
        int m = bm + ty * 4 + ((ii < 4) ? ii : (60 + ii));  // +64 offset for ii>=4
        float4 o0, o1;
        o0.x = acc[ii][0] + b0[0]; o0.y = acc[ii][1] + b0[1];
        o0.z = acc[ii][2] + b0[2]; o0.w = acc[ii][3] + b0[3];
        o1.x = acc[ii][4] + b1[0]; o1.y = acc[ii][5] + b1[1];
        o1.z = acc[ii][6] + b1[2]; o1.w = acc[ii][7] + b1[3];
        *(float4*)&X[(size_t)m * G4H + gn0]      = o0;
        *(float4*)&X[(size_t)m * G4H + gn0 + 64] = o1;
    }
}

// ============================================================================
// Kernel B: one LSTM step.
//   grid = 128 CTAs, 256 threads. CTA `cta` owns h-columns [cta*8, cta*8+8).
//   gates[b][row] = Xg[b][row] + sum_k h_prev[b][k] * V[row][k]
//   row = gate*1024 + cta*8 + jl, gate in {i,f,g,o}.
//   Thread: j = tid>>3 (gate*8+jl), bg = tid&7, batches b = bg + 8*i, i=0..3.
//   h_prev staged in smem, row stride 1028 floats => bank spacing 4 between
//   the 8 distinct LDS.128 addresses per warp -> conflict-free.
// ============================================================================
#define HPAD 1028
#define STEP_SMEM (BB * HPAD * 4)   // 131584 bytes

__global__ void __launch_bounds__(256) lstm_step_kernel(
    const float* __restrict__ Xg,     // [B][4096] for this step
    const float* __restrict__ h_prev, // [B][1024]
    const float* __restrict__ c_prev, // [B][1024]
    const float* __restrict__ V,      // [4096][1024]
    float* __restrict__ h_out1,
    float* __restrict__ h_out2,
    float* __restrict__ c_out)
{
    extern __shared__ float sm[];
    float* h_s = sm;

    const int tid = threadIdx.x;
    const int cta = blockIdx.x;

    // stage h_prev (128 KB) into smem, float4, coalesced
    #pragma unroll
    for (int idx = tid; idx < BB * (HH / 4); idx += 256) {
        const int b  = idx >> 8;    // idx / 256
        const int k4 = idx & 255;
        float4 v = ((const float4*)h_prev)[idx];
        *(float4*)&h_s[b * HPAD + k4 * 4] = v;
    }
    __syncthreads();

    const int j    = tid >> 3;     // 0..31
    const int bg   = tid & 7;
    const int gate = j >> 3;
    const int jl   = j & 7;
    const int row  = gate * HH + cta * 8 + jl;

    const float4* Vr = (const float4*)(V + (size_t)row * HH);
    const float* hb0 = h_s + (bg + 0)  * HPAD;
    const float* hb1 = h_s + (bg + 8)  * HPAD;
    const float* hb2 = h_s + (bg + 16) * HPAD;
    const float* hb3 = h_s + (bg + 24) * HPAD;

    float acc0 = Xg[(size_t)(bg + 0)  * G4H + row];
    float acc1 = Xg[(size_t)(bg + 8)  * G4H + row];
    float acc2 = Xg[(size_t)(bg + 16) * G4H + row];
    float acc3 = Xg[(size_t)(bg + 24) * G4H + row];

    #pragma unroll 4
    for (int k4 = 0; k4 < HH / 4; k4++) {
        const float4 v  = __ldg(&Vr[k4]);
        const float4 h0 = *(const float4*)(hb0 + 4 * k4);
        const float4 h1 = *(const float4*)(hb1 + 4 * k4);
        const float4 h2 = *(const float4*)(hb2 + 4 * k4);
        const float4 h3 = *(const float4*)(hb3 + 4 * k4);
        acc0 += h0.x * v.x + h0.y * v.y + h0.z * v.z + h0.w * v.w;
        acc1 += h1.x * v.x + h1.y * v.y + h1.z * v.z + h1.w * v.w;
        acc2 += h2.x * v.x + h2.y * v.y + h2.z * v.z + h2.w * v.w;
        acc3 += h3.x * v.x + h3.y * v.y + h3.z * v.z + h3.w * v.w;
    }

    // exchange gates via smem (reuse h_s space), then elementwise
    __syncthreads();
    float* gbuf = sm;   // [4 gates][32 b][8 cols] = 1024 floats
    gbuf[(gate * BB + (bg + 0))  * 8 + jl] = acc0;
    gbuf[(gate * BB + (bg + 8))  * 8 + jl] = acc1;
    gbuf[(gate * BB + (bg + 16)) * 8 + jl] = acc2;
    gbuf[(gate * BB + (bg + 24)) * 8 + jl] = acc3;
    __syncthreads();

    const int b  = tid >> 3;   // 0..31
    const int l2 = tid & 7;    // 0..7
    const float xi = gbuf[(0 * BB + b) * 8 + l2];
    const float xf = gbuf[(1 * BB + b) * 8 + l2];
    const float xg = gbuf[(2 * BB + b) * 8 + l2];
    const float xo = gbuf[(3 * BB + b) * 8 + l2];

    const float iv = 1.f / (1.f + __expf(-xi));
    const float fv = 1.f / (1.f + __expf(-xf));
    const float gv = tanhf(xg);
    const float ov = 1.f / (1.f + __expf(-xo));

    const int col = cta * 8 + l2;
    const float cp = c_prev[b * HH + col];
    const float cn = fv * cp + iv * gv;
    const float hn = ov * tanhf(cn);

    h_out1[b * HH + col] = hn;
    h_out2[b * HH + col] = hn;
    c_out[b * HH + col]  = cn;
}

// final state copy: h_f = all_h[S-1], c_f = all_c[S-1]
__global__ void copy_final_kernel(const float* __restrict__ h_last,
                                  const float* __restrict__ c_last,
                                  float* __restrict__ h_f,
                                  float* __restrict__ c_f)
{
    int i = blockIdx.x * blockDim.x + threadIdx.x;
    if (i < BH) {
        h_f[i] = h_last[i];
        c_f[i] = c_last[i];
    }
}

// ============================================================================
// Launch
// ============================================================================
extern "C" void kernel_launch(void* const* d_in, const int* in_sizes, int n_in,
                              void* d_out, int out_size)
{
    const float* layer_input = (const float*)d_in[0];  // [S,B,D]
    const float* h_t         = (const float*)d_in[1];  // [B,H]
    const float* c_t         = (const float*)d_in[2];  // [B,H]
    const float* U           = (const float*)d_in[3];  // [4H,D]
    const float* V           = (const float*)d_in[4];  // [4H,H]
    const float* bih         = (const float*)d_in[5];  // [4H]
    const float* bhh         = (const float*)d_in[6];  // [4H]

    float* out = (float*)d_out;
    // output tuple: (all_h, h_f, c_f, all_h, all_c)
    float* all_h1 = out;
    float* h_f    = out + (size_t)SS * BH;
    float* c_f    = h_f + BH;
    float* all_h2 = c_f + BH;
    float* all_c  = all_h2 + (size_t)SS * BH;

    float* Xp = nullptr;
    cudaGetSymbolAddress((void**)&Xp, g_X);

    cudaFuncSetAttribute(lstm_step_kernel,
                         cudaFuncAttributeMaxDynamicSharedMemorySize, STEP_SMEM);

    // Kernel A: input projection + bias
    dim3 gg(G4H / 128, (SS * BB) / 128);   // (32, 128)
    gemm_x_kernel<<<gg, 256>>>(layer_input, U, bih, bhh, Xp);

    // Kernel B: 512 sequential steps (stream-ordered)
    for (int s = 0; s < SS; s++) {
        const float* hp = (s == 0) ? h_t : all_h1 + (size_t)(s - 1) * BH;
        const float* cp = (s == 0) ? c_t : all_c  + (size_t)(s - 1) * BH;
        lstm_step_kernel<<<128, 256, STEP_SMEM>>>(
            Xp + (size_t)s * BB * G4H, hp, cp, V,
            all_h1 + (size_t)s * BH,
            all_h2 + (size_t)s * BH,
            all_c  + (size_t)s * BH);
    }

    copy_final_kernel<<<(BH + 255) / 256, 256>>>(
        all_h1 + (size_t)(SS - 1) * BH,
        all_c  + (size_t)(SS - 1) * BH,
        h_f, c_f);
}